// round 12
// baseline (speedup 1.0000x reference)
#include <cuda_runtime.h>
#include <cuda_fp16.h>
#include <math.h>
#include <stdint.h>

#define N_NODES 50000
#define N_PAD   53248            // padded for int4 scan reads
#define N_EDGES 800000
#define E_TOT   (N_EDGES + N_NODES)   // with self loops
#define HID     128
#define NEG_SLOPE 0.2f
#define EPS 1e-16f

#define M_TILE   128
#define M_BLOCKS ((N_NODES + M_TILE - 1) / M_TILE)   // 391
#define BK 32                 // k per chunk (16 half2 pairs)
#define A_P2 20               // half2 pitch for A tiles
#define B_P2 132              // half2 pitch for B chunk
#define BUF_2 (2 * M_TILE * A_P2 + 16 * B_P2)        // 7232 half2 per buffer
#define GEMM_DYN_SMEM (2 * BUF_2 * 4)                // 57856 B (double buffered)

// ---------------- scratch (device globals; no allocation allowed) -----------
__device__ __half  g_xh[(size_t)N_NODES * HID];  // x = h @ W, fp16 (gather source)
__device__ float   g_h [(size_t)N_NODES * HID];  // layer activations (fp32)
__device__ float   g_as[N_NODES];
__device__ float   g_ad[N_NODES];
__device__ __half2 g_wb[3 * 64 * HID];           // W pair-packed fp16: [l][k/2][n]
__device__ int     g_deg[N_PAD];
__device__ int     g_off[N_NODES + 1];
__device__ int     g_cur[N_NODES];
__device__ int     g_csrc[E_TOT];

// ---------------- helpers -----------------------------------------------------
__device__ __forceinline__ void mma_f16(float* d, const uint32_t* a, const uint32_t* b) {
    asm volatile(
        "mma.sync.aligned.m16n8k16.row.col.f32.f16.f16.f32 "
        "{%0,%1,%2,%3}, {%4,%5,%6,%7}, {%8,%9}, {%0,%1,%2,%3};"
        : "+f"(d[0]), "+f"(d[1]), "+f"(d[2]), "+f"(d[3])
        : "r"(a[0]), "r"(a[1]), "r"(a[2]), "r"(a[3]), "r"(b[0]), "r"(b[1]));
}

// ---------------- prep: W -> pair-packed fp16 image --------------------------
__global__ void prep_w_kernel(const float* __restrict__ Ws) {
    int idx = blockIdx.x * blockDim.x + threadIdx.x;   // over 3*64*128
    if (idx >= 3 * 64 * HID) return;
    int l   = idx / (64 * HID);
    int rem = idx - l * 64 * HID;
    int p = rem >> 7, n = rem & 127;
    const float* W = Ws + (size_t)l * HID * HID;
    g_wb[idx] = __floats2half2_rn(W[(2 * p) * HID + n], W[(2 * p + 1) * HID + n]);
}

// ---------------- CSR build (4 edges/thread) ----------------------------------
__global__ void count_kernel(const int* __restrict__ ei) {
    int t = blockIdx.x * blockDim.x + threadIdx.x;     // over N_EDGES/4
    if (t >= N_EDGES / 4) return;
    int4 d4 = ((const int4*)(ei + N_EDGES))[t];
    atomicAdd(&g_deg[d4.x], 1);
    atomicAdd(&g_deg[d4.y], 1);
    atomicAdd(&g_deg[d4.z], 1);
    atomicAdd(&g_deg[d4.w], 1);
}
// single-block exclusive scan, 4 elements/thread; +1/node folds in self-loops
__global__ void scan_kernel() {
    __shared__ int warp_sums[32];
    __shared__ int s_carry;
    int tid = threadIdx.x, lane = tid & 31, wid = tid >> 5;
    if (tid == 0) { g_off[0] = 0; s_carry = 0; }
    __syncthreads();
    for (int base = 0; base < N_NODES; base += 4096) {
        int i = base + tid * 4;
        int4 v = *(const int4*)(g_deg + i);            // padded zeros beyond N_NODES
        int sl = (i < N_NODES) ? 1 : 0;                // self-loop (N_NODES % 4 == 0)
        int t0 = v.x + sl, t1 = t0 + v.y + sl, t2 = t1 + v.z + sl, t3 = t2 + v.w + sl;
        int x = t3;
        #pragma unroll
        for (int d = 1; d < 32; d <<= 1) {
            int t = __shfl_up_sync(0xffffffffu, x, d);
            if (lane >= d) x += t;
        }
        if (lane == 31) warp_sums[wid] = x;
        __syncthreads();
        if (wid == 0) {
            int w = warp_sums[lane];
            #pragma unroll
            for (int d = 1; d < 32; d <<= 1) {
                int t = __shfl_up_sync(0xffffffffu, w, d);
                if (lane >= d) w += t;
            }
            warp_sums[lane] = w;
        }
        __syncthreads();
        int excl = x - t3 + ((wid > 0) ? warp_sums[wid - 1] : 0) + s_carry;
        if (i < N_NODES) {
            g_off[i + 1] = excl + t0; g_cur[i + 0] = excl;
            g_off[i + 2] = excl + t1; g_cur[i + 1] = excl + t0;
            g_off[i + 3] = excl + t2; g_cur[i + 2] = excl + t1;
            g_off[i + 4] = excl + t3; g_cur[i + 3] = excl + t2;
        }
        __syncthreads();
        if (tid == 1023) s_carry = excl + t3;
        __syncthreads();
    }
}
__global__ void fill_kernel(const int* __restrict__ ei) {
    int t = blockIdx.x * blockDim.x + threadIdx.x;
    if (t < N_EDGES / 4) {
        int4 s4 = ((const int4*)ei)[t];
        int4 d4 = ((const int4*)(ei + N_EDGES))[t];
        g_csrc[atomicAdd(&g_cur[d4.x], 1)] = s4.x;
        g_csrc[atomicAdd(&g_cur[d4.y], 1)] = s4.y;
        g_csrc[atomicAdd(&g_cur[d4.z], 1)] = s4.z;
        g_csrc[atomicAdd(&g_cur[d4.w], 1)] = s4.w;
    } else {
        int node = t - N_EDGES / 4;
        if (node < N_NODES)
            g_csrc[atomicAdd(&g_cur[node], 1)] = node;   // self loop
    }
}

// ---------------- GEMM: fp16 m16n8k16 2-term, double-buffered chunks ---------
__global__ void __launch_bounds__(256, 2)
gemm_mma_kernel(const float* __restrict__ in, const __half2* __restrict__ Wb,
                const float* __restrict__ a_s, const float* __restrict__ a_d)
{
    extern __shared__ __half2 dsm[];
    // per-buffer layout: [sAh2: 128*A_P2][sAl2: 128*A_P2][sB2: 16*B_P2]

    __shared__ float s_as[HID], s_ad[HID];
    __shared__ float s_ps[2][M_TILE], s_pd[2][M_TILE];

    int tid = threadIdx.x, lane = tid & 31, wid = tid >> 5;
    int wm = wid & 3;        // warp M tile: 32 rows
    int wn = wid >> 2;       // warp N tile: 64 cols
    int m0 = blockIdx.x * M_TILE;
    int q = lane & 3, g = lane >> 2;

    for (int i = tid; i < HID; i += 256) { s_as[i] = a_s[i]; s_ad[i] = a_d[i]; }

    int a_row = tid >> 3;          // + it*32
    int a_kq  = (tid & 7) * 4;     // k within chunk (floats)
    int a_p0  = (tid & 7) * 2;     // half2 pair col
    int b_row = tid >> 4;          // 0..15 (pair within chunk)
    int b_c16 = (tid & 15) * 8;    // half2 col base

    float acc[2][8][4];
    #pragma unroll
    for (int mi = 0; mi < 2; mi++)
        #pragma unroll
        for (int ni = 0; ni < 8; ni++)
            #pragma unroll
            for (int t = 0; t < 4; t++) acc[mi][ni][t] = 0.f;

    const uint4* wb4 = (const uint4*)Wb;       // [64][32] uint4

    float4 rA[4]; uint4 rB[2];
    // prologue: load + stage chunk 0 into buffer 0
    #pragma unroll
    for (int it = 0; it < 4; it++) {
        int gr = m0 + it * 32 + a_row;
        rA[it] = make_float4(0.f, 0.f, 0.f, 0.f);
        if (gr < N_NODES) rA[it] = *(const float4*)(in + (size_t)gr * HID + a_kq);
    }
    rB[0] = wb4[b_row * 32 + (tid & 15) * 2];
    rB[1] = wb4[b_row * 32 + (tid & 15) * 2 + 1];
    {
        __half2* sAh2 = dsm;
        __half2* sAl2 = sAh2 + M_TILE * A_P2;
        __half2* sB2  = sAl2 + M_TILE * A_P2;
        #pragma unroll
        for (int it = 0; it < 4; it++) {
            float4 v = rA[it];
            __half2 h01 = __floats2half2_rn(v.x, v.y);
            __half2 h23 = __floats2half2_rn(v.z, v.w);
            float2 f01 = __half22float2(h01);
            float2 f23 = __half22float2(h23);
            __half2 l01 = __floats2half2_rn(v.x - f01.x, v.y - f01.y);
            __half2 l23 = __floats2half2_rn(v.z - f23.x, v.w - f23.y);
            int row = it * 32 + a_row;
            *(uint32_t*)&sAh2[row * A_P2 + a_p0]     = *(uint32_t*)&h01;
            *(uint32_t*)&sAh2[row * A_P2 + a_p0 + 1] = *(uint32_t*)&h23;
            *(uint32_t*)&sAl2[row * A_P2 + a_p0]     = *(uint32_t*)&l01;
            *(uint32_t*)&sAl2[row * A_P2 + a_p0 + 1] = *(uint32_t*)&l23;
        }
        *(uint4*)&sB2[b_row * B_P2 + b_c16]     = rB[0];
        *(uint4*)&sB2[b_row * B_P2 + b_c16 + 4] = rB[1];
    }
    __syncthreads();

    #pragma unroll
    for (int c = 0; c < 4; c++) {
        // prefetch chunk c+1 into registers
        if (c < 3) {
            #pragma unroll
            for (int it = 0; it < 4; it++) {
                int gr = m0 + it * 32 + a_row;
                rA[it] = make_float4(0.f, 0.f, 0.f, 0.f);
                if (gr < N_NODES)
                    rA[it] = *(const float4*)(in + (size_t)gr * HID + (c + 1) * BK + a_kq);
            }
            int pr = 16 * (c + 1) + b_row;
            rB[0] = wb4[pr * 32 + (tid & 15) * 2];
            rB[1] = wb4[pr * 32 + (tid & 15) * 2 + 1];
        }

        // MMA chain on buffer c&1
        {
            const uint32_t* base = (const uint32_t*)(dsm + (c & 1) * BUF_2);
            const uint32_t* sAhu = base;
            const uint32_t* sAlu = base + M_TILE * A_P2;
            const uint32_t* sBu  = base + 2 * M_TILE * A_P2;
            #pragma unroll
            for (int ks = 0; ks < 2; ks++) {
                int kp = ks * 8;
                uint32_t ah[2][4], al[2][4];
                #pragma unroll
                for (int mi = 0; mi < 2; mi++) {
                    int r = wm * 32 + g + mi * 16;
                    const uint32_t* ph = sAhu + r * A_P2;
                    const uint32_t* pl = sAlu + r * A_P2;
                    ah[mi][0] = ph[kp + q];            ah[mi][1] = ph[8 * A_P2 + kp + q];
                    ah[mi][2] = ph[kp + q + 4];        ah[mi][3] = ph[8 * A_P2 + kp + q + 4];
                    al[mi][0] = pl[kp + q];            al[mi][1] = pl[8 * A_P2 + kp + q];
                    al[mi][2] = pl[kp + q + 4];        al[mi][3] = pl[8 * A_P2 + kp + q + 4];
                }
                #pragma unroll
                for (int ni = 0; ni < 8; ni++) {
                    int cc = wn * 64 + ni * 8 + g;
                    const uint32_t* pb = sBu + (kp + q) * B_P2 + cc;
                    uint32_t b[2] = { pb[0], pb[4 * B_P2] };
                    #pragma unroll
                    for (int mi = 0; mi < 2; mi++) {
                        mma_f16(acc[mi][ni], ah[mi], b);
                        mma_f16(acc[mi][ni], al[mi], b);
                    }
                }
            }
        }

        // stage chunk c+1 into the other buffer (nobody reads it this iter)
        if (c < 3) {
            __half2* buf  = dsm + ((c + 1) & 1) * BUF_2;
            __half2* sAh2 = buf;
            __half2* sAl2 = sAh2 + M_TILE * A_P2;
            __half2* sB2  = sAl2 + M_TILE * A_P2;
            #pragma unroll
            for (int it = 0; it < 4; it++) {
                float4 v = rA[it];
                __half2 h01 = __floats2half2_rn(v.x, v.y);
                __half2 h23 = __floats2half2_rn(v.z, v.w);
                float2 f01 = __half22float2(h01);
                float2 f23 = __half22float2(h23);
                __half2 l01 = __floats2half2_rn(v.x - f01.x, v.y - f01.y);
                __half2 l23 = __floats2half2_rn(v.z - f23.x, v.w - f23.y);
                int row = it * 32 + a_row;
                *(uint32_t*)&sAh2[row * A_P2 + a_p0]     = *(uint32_t*)&h01;
                *(uint32_t*)&sAh2[row * A_P2 + a_p0 + 1] = *(uint32_t*)&h23;
                *(uint32_t*)&sAl2[row * A_P2 + a_p0]     = *(uint32_t*)&l01;
                *(uint32_t*)&sAl2[row * A_P2 + a_p0 + 1] = *(uint32_t*)&l23;
            }
            *(uint4*)&sB2[b_row * B_P2 + b_c16]     = rB[0];
            *(uint4*)&sB2[b_row * B_P2 + b_c16 + 4] = rB[1];
            __syncthreads();
        }
    }

    // epilogue: store g_xh (fp16) + fused alpha partial dots (fp32, exact)
    #pragma unroll
    for (int mi = 0; mi < 2; mi++) {
        int rA_ = wm * 32 + g + mi * 16;
        int rB_ = rA_ + 8;
        int gA = m0 + rA_, gB = m0 + rB_;
        float sA_ = 0.f, dA_ = 0.f, sB_ = 0.f, dB_ = 0.f;
        #pragma unroll
        for (int ni = 0; ni < 8; ni++) {
            int cc = wn * 64 + ni * 8 + q * 2;
            float v0 = acc[mi][ni][0], v1 = acc[mi][ni][1];
            float v2 = acc[mi][ni][2], v3 = acc[mi][ni][3];
            sA_ += v0 * s_as[cc] + v1 * s_as[cc + 1];
            dA_ += v0 * s_ad[cc] + v1 * s_ad[cc + 1];
            sB_ += v2 * s_as[cc] + v3 * s_as[cc + 1];
            dB_ += v2 * s_ad[cc] + v3 * s_ad[cc + 1];
            if (gA < N_NODES)
                *(__half2*)(g_xh + (size_t)gA * HID + cc) = __floats2half2_rn(v0, v1);
            if (gB < N_NODES)
                *(__half2*)(g_xh + (size_t)gB * HID + cc) = __floats2half2_rn(v2, v3);
        }
        sA_ += __shfl_xor_sync(0xffffffffu, sA_, 1); sA_ += __shfl_xor_sync(0xffffffffu, sA_, 2);
        dA_ += __shfl_xor_sync(0xffffffffu, dA_, 1); dA_ += __shfl_xor_sync(0xffffffffu, dA_, 2);
        sB_ += __shfl_xor_sync(0xffffffffu, sB_, 1); sB_ += __shfl_xor_sync(0xffffffffu, sB_, 2);
        dB_ += __shfl_xor_sync(0xffffffffu, dB_, 1); dB_ += __shfl_xor_sync(0xffffffffu, dB_, 2);
        if (q == 0) {
            s_ps[wn][rA_] = sA_; s_pd[wn][rA_] = dA_;
            s_ps[wn][rB_] = sB_; s_pd[wn][rB_] = dB_;
        }
    }
    __syncthreads();
    if (tid < M_TILE) {
        int gm = m0 + tid;
        if (gm < N_NODES) {
            g_as[gm] = s_ps[0][tid] + s_ps[1][tid];
            g_ad[gm] = s_pd[0][tid] + s_pd[1][tid];
        }
    }
}

// ---------------- aggregation: warp/node, online softmax, MLP-4 gather -------
__device__ __forceinline__ float leaky(float t) {
    return t > 0.f ? t : NEG_SLOPE * t;
}

__global__ __launch_bounds__(256) void agg_kernel(
    const float* __restrict__ bias, float* __restrict__ dout, int last)
{
    __shared__ uint2 s_ew[8][32];    // per-warp (w, src) pair table
    int node = (blockIdx.x * blockDim.x + threadIdx.x) >> 5;
    int lane = threadIdx.x & 31;
    int wid  = (threadIdx.x >> 5) & 7;
    if (node >= N_NODES) return;
    int start = g_off[node];
    int end   = g_off[node + 1];
    float adv = g_ad[node];

    float m = -INFINITY;
    float den = 0.f;
    float4 acc = make_float4(0.f, 0.f, 0.f, 0.f);

    for (int i0 = start; i0 < end; i0 += 32) {
        int n = end - i0; if (n > 32) n = 32;
        int   s_l = 0; float e_l = -INFINITY;
        if (lane < n) {
            s_l = g_csrc[i0 + lane];
            e_l = leaky(g_as[s_l] + adv);
        }
        float bm = e_l;
        #pragma unroll
        for (int o = 16; o; o >>= 1) bm = fmaxf(bm, __shfl_xor_sync(0xffffffffu, bm, o));
        if (bm > m) {
            float f = __expf(m - bm);
            acc.x *= f; acc.y *= f; acc.z *= f; acc.w *= f;
            den *= f;
            m = bm;
        }
        float w_l = (lane < n) ? __expf(e_l - m) : 0.f;
        den += w_l;
        s_ew[wid][lane] = make_uint2(__float_as_uint(w_l), (uint32_t)s_l);
        __syncwarp();

        int j = 0;
        // 4-way batched gather: 4 LDGs in flight per warp
        for (; j + 4 <= n; j += 4) {
            uint2 e0 = s_ew[wid][j],     e1 = s_ew[wid][j + 1];
            uint2 e2 = s_ew[wid][j + 2], e3 = s_ew[wid][j + 3];
            uint2 r0 = *((const uint2*)(g_xh + (size_t)e0.y * HID) + lane);
            uint2 r1 = *((const uint2*)(g_xh + (size_t)e1.y * HID) + lane);
            uint2 r2 = *((const uint2*)(g_xh + (size_t)e2.y * HID) + lane);
            uint2 r3 = *((const uint2*)(g_xh + (size_t)e3.y * HID) + lane);
            float w0 = __uint_as_float(e0.x), w1 = __uint_as_float(e1.x);
            float w2 = __uint_as_float(e2.x), w3 = __uint_as_float(e3.x);
            float2 a0 = __half22float2(*(const __half2*)&r0.x);
            float2 b0 = __half22float2(*(const __half2*)&r0.y);
            acc.x += w0 * a0.x; acc.y += w0 * a0.y; acc.z += w0 * b0.x; acc.w += w0 * b0.y;
            float2 a1 = __half22float2(*(const __half2*)&r1.x);
            float2 b1 = __half22float2(*(const __half2*)&r1.y);
            acc.x += w1 * a1.x; acc.y += w1 * a1.y; acc.z += w1 * b1.x; acc.w += w1 * b1.y;
            float2 a2 = __half22float2(*(const __half2*)&r2.x);
            float2 b2 = __half22float2(*(const __half2*)&r2.y);
            acc.x += w2 * a2.x; acc.y += w2 * a2.y; acc.z += w2 * b2.x; acc.w += w2 * b2.y;
            float2 a3 = __half22float2(*(const __half2*)&r3.x);
            float2 b3 = __half22float2(*(const __half2*)&r3.y);
            acc.x += w3 * a3.x; acc.y += w3 * a3.y; acc.z += w3 * b3.x; acc.w += w3 * b3.y;
        }
        for (; j < n; j++) {
            uint2 ew = s_ew[wid][j];
            float w = __uint_as_float(ew.x);
            uint2 raw = *((const uint2*)(g_xh + (size_t)ew.y * HID) + lane);
            float2 f0 = __half22float2(*(const __half2*)&raw.x);
            float2 f1 = __half22float2(*(const __half2*)&raw.y);
            acc.x += w * f0.x; acc.y += w * f0.y;
            acc.z += w * f1.x; acc.w += w * f1.y;
        }
        __syncwarp();
    }
    #pragma unroll
    for (int o = 16; o; o >>= 1) den += __shfl_xor_sync(0xffffffffu, den, o);
    float inv = 1.0f / (den + EPS);

    float4 b4 = *(const float4*)(bias + lane * 4);
    acc.x = acc.x * inv + b4.x; acc.y = acc.y * inv + b4.y;
    acc.z = acc.z * inv + b4.z; acc.w = acc.w * inv + b4.w;

    if (last) {
        *(float4*)(dout + (size_t)node * HID + lane * 4) = acc;
    } else {
        acc.x = fmaxf(acc.x, 0.f); acc.y = fmaxf(acc.y, 0.f);
        acc.z = fmaxf(acc.z, 0.f); acc.w = fmaxf(acc.w, 0.f);
        *(float4*)(g_h + (size_t)node * HID + lane * 4) = acc;
    }
}

// ---------------- launch -----------------------------------------------------
extern "C" void kernel_launch(void* const* d_in, const int* in_sizes, int n_in,
                              void* d_out, int out_size)
{
    const float* z     = (const float*)d_in[0];
    const int*   ei    = (const int*)  d_in[1];
    const float* Ws    = (const float*)d_in[2];
    const float* a_src = (const float*)d_in[3];
    const float* a_dst = (const float*)d_in[4];
    const float* bias  = (const float*)d_in[5];
    float* out = (float*)d_out;

    cudaFuncSetAttribute(gemm_mma_kernel, cudaFuncAttributeMaxDynamicSharedMemorySize,
                         GEMM_DYN_SMEM);

    float*   d_gh;  cudaGetSymbolAddress((void**)&d_gh, g_h);
    __half2* d_wb;  cudaGetSymbolAddress((void**)&d_wb, g_wb);
    int*     d_deg; cudaGetSymbolAddress((void**)&d_deg, g_deg);

    int warp_blocks = (N_NODES * 32 + 255) / 256;

    cudaMemsetAsync(d_deg, 0, N_PAD * sizeof(int));
    prep_w_kernel<<<(3 * 64 * HID + 255) / 256, 256>>>(Ws);          // launch 1
    count_kernel<<<(N_EDGES / 4 + 255) / 256, 256>>>(ei);            // launch 2
    scan_kernel<<<1, 1024>>>();                                      // launch 3
    // launch 4 = gemm0 (ncu capture slot)
    gemm_mma_kernel<<<M_BLOCKS, 256, GEMM_DYN_SMEM>>>(z, d_wb, a_src, a_dst);
    fill_kernel<<<(N_EDGES / 4 + N_NODES + 255) / 256, 256>>>(ei);   // launch 5
    agg_kernel<<<warp_blocks, 256>>>(bias, out, 0);

    for (int l = 1; l < 3; l++) {
        gemm_mma_kernel<<<M_BLOCKS, 256, GEMM_DYN_SMEM>>>(
            d_gh, d_wb + (size_t)l * 64 * HID, a_src + l * HID, a_dst + l * HID);
        agg_kernel<<<warp_blocks, 256>>>(bias + l * HID, out, l == 2);
    }
}

// round 13
// speedup vs baseline: 1.0475x; 1.0475x over previous
#include <cuda_runtime.h>
#include <cuda_fp16.h>
#include <math.h>
#include <stdint.h>

#define N_NODES 50000
#define N_PAD   53248            // padded for int4 scan reads
#define N_EDGES 800000
#define E_TOT   (N_EDGES + N_NODES)   // with self loops
#define HID     128
#define NEG_SLOPE 0.2f
#define EPS 1e-16f

#define M_TILE   128
#define M_BLOCKS ((N_NODES + M_TILE - 1) / M_TILE)   // 391
#define BK 32                 // k (fp16 elems) per chunk
#define A_PH 40               // half pitch for A tiles (32 + 8 pad) -> 80B rows
#define B_PH 136              // half pitch for B chunk (128 + 8)    -> 272B rows
// sAh + sAl ([128][A_PH] each) + sB ([32][B_PH]), half (2 B) units
#define GEMM_DYN_SMEM ((2 * M_TILE * A_PH + BK * B_PH) * 2)   // 29184 B

// ---------------- scratch (device globals; no allocation allowed) -----------
__device__ __half  g_xh[(size_t)N_NODES * HID];  // x = h @ W, fp16 (gather source)
__device__ float   g_h [(size_t)N_NODES * HID];  // layer activations (fp32)
__device__ float   g_as[N_NODES];
__device__ float   g_ad[N_NODES];
__device__ __half  g_wh[3 * HID * HID];          // W fp16 image: [l][k][n]
__device__ int     g_deg[N_PAD];
__device__ int     g_off[N_NODES + 1];
__device__ int     g_cur[N_NODES];
__device__ int     g_csrc[E_TOT];

// ---------------- helpers -----------------------------------------------------
__device__ __forceinline__ void mma_f16(float* d, const uint32_t* a, const uint32_t* b) {
    asm volatile(
        "mma.sync.aligned.m16n8k16.row.col.f32.f16.f16.f32 "
        "{%0,%1,%2,%3}, {%4,%5,%6,%7}, {%8,%9}, {%0,%1,%2,%3};"
        : "+f"(d[0]), "+f"(d[1]), "+f"(d[2]), "+f"(d[3])
        : "r"(a[0]), "r"(a[1]), "r"(a[2]), "r"(a[3]), "r"(b[0]), "r"(b[1]));
}
#define LDSM_X4(R0, R1, R2, R3, ADDR) \
    asm volatile("ldmatrix.sync.aligned.m8n8.x4.shared.b16 {%0,%1,%2,%3}, [%4];" \
        : "=r"(R0), "=r"(R1), "=r"(R2), "=r"(R3) : "r"(ADDR))
#define LDSM_X4T(R0, R1, R2, R3, ADDR) \
    asm volatile("ldmatrix.sync.aligned.m8n8.x4.trans.shared.b16 {%0,%1,%2,%3}, [%4];" \
        : "=r"(R0), "=r"(R1), "=r"(R2), "=r"(R3) : "r"(ADDR))

// ---------------- prep: W -> plain fp16 image [l][k][n] ----------------------
__global__ void prep_w_kernel(const float* __restrict__ Ws) {
    int i = blockIdx.x * blockDim.x + threadIdx.x;   // over 3*128*128/2 half2
    if (i >= 3 * HID * HID / 2) return;
    float2 v = ((const float2*)Ws)[i];
    ((__half2*)g_wh)[i] = __floats2half2_rn(v.x, v.y);
}

// ---------------- CSR build (4 edges/thread) ----------------------------------
__global__ void count_kernel(const int* __restrict__ ei) {
    int t = blockIdx.x * blockDim.x + threadIdx.x;     // over N_EDGES/4
    if (t >= N_EDGES / 4) return;
    int4 d4 = ((const int4*)(ei + N_EDGES))[t];
    atomicAdd(&g_deg[d4.x], 1);
    atomicAdd(&g_deg[d4.y], 1);
    atomicAdd(&g_deg[d4.z], 1);
    atomicAdd(&g_deg[d4.w], 1);
}
// single-block exclusive scan, 4 elements/thread; +1/node folds in self-loops
__global__ void scan_kernel() {
    __shared__ int warp_sums[32];
    __shared__ int s_carry;
    int tid = threadIdx.x, lane = tid & 31, wid = tid >> 5;
    if (tid == 0) { g_off[0] = 0; s_carry = 0; }
    __syncthreads();
    for (int base = 0; base < N_NODES; base += 4096) {
        int i = base + tid * 4;
        int4 v = *(const int4*)(g_deg + i);            // padded zeros beyond N_NODES
        int sl = (i < N_NODES) ? 1 : 0;                // self-loop (N_NODES % 4 == 0)
        int t0 = v.x + sl, t1 = t0 + v.y + sl, t2 = t1 + v.z + sl, t3 = t2 + v.w + sl;
        int x = t3;
        #pragma unroll
        for (int d = 1; d < 32; d <<= 1) {
            int t = __shfl_up_sync(0xffffffffu, x, d);
            if (lane >= d) x += t;
        }
        if (lane == 31) warp_sums[wid] = x;
        __syncthreads();
        if (wid == 0) {
            int w = warp_sums[lane];
            #pragma unroll
            for (int d = 1; d < 32; d <<= 1) {
                int t = __shfl_up_sync(0xffffffffu, w, d);
                if (lane >= d) w += t;
            }
            warp_sums[lane] = w;
        }
        __syncthreads();
        int excl = x - t3 + ((wid > 0) ? warp_sums[wid - 1] : 0) + s_carry;
        if (i < N_NODES) {
            g_off[i + 1] = excl + t0; g_cur[i + 0] = excl;
            g_off[i + 2] = excl + t1; g_cur[i + 1] = excl + t0;
            g_off[i + 3] = excl + t2; g_cur[i + 2] = excl + t1;
            g_off[i + 4] = excl + t3; g_cur[i + 3] = excl + t2;
        }
        __syncthreads();
        if (tid == 1023) s_carry = excl + t3;
        __syncthreads();
    }
}
__global__ void fill_kernel(const int* __restrict__ ei) {
    int t = blockIdx.x * blockDim.x + threadIdx.x;
    if (t < N_EDGES / 4) {
        int4 s4 = ((const int4*)ei)[t];
        int4 d4 = ((const int4*)(ei + N_EDGES))[t];
        g_csrc[atomicAdd(&g_cur[d4.x], 1)] = s4.x;
        g_csrc[atomicAdd(&g_cur[d4.y], 1)] = s4.y;
        g_csrc[atomicAdd(&g_cur[d4.z], 1)] = s4.z;
        g_csrc[atomicAdd(&g_cur[d4.w], 1)] = s4.w;
    } else {
        int node = t - N_EDGES / 4;
        if (node < N_NODES)
            g_csrc[atomicAdd(&g_cur[node], 1)] = node;   // self loop
    }
}

// ---------------- GEMM: fp16 m16n8k16 2-term, ldmatrix fragment loads --------
__global__ void __launch_bounds__(256, 2)
gemm_mma_kernel(const float* __restrict__ in, const __half* __restrict__ Wh,
                const float* __restrict__ a_s, const float* __restrict__ a_d)
{
    extern __shared__ __half dsm[];
    __half* sAh = dsm;                        // [M_TILE][A_PH]
    __half* sAl = sAh + M_TILE * A_PH;        // [M_TILE][A_PH]
    __half* sB  = sAl + M_TILE * A_PH;        // [BK][B_PH]  (k rows, n cols)

    __shared__ float s_as[HID], s_ad[HID];
    __shared__ float s_ps[2][M_TILE], s_pd[2][M_TILE];

    int tid = threadIdx.x, lane = tid & 31, wid = tid >> 5;
    int wm = wid & 3;        // warp M tile: 32 rows
    int wn = wid >> 2;       // warp N tile: 64 cols
    int m0 = blockIdx.x * M_TILE;
    int q = lane & 3, g = lane >> 2;

    for (int i = tid; i < HID; i += 256) { s_as[i] = a_s[i]; s_ad[i] = a_d[i]; }

    // staging addressing
    int a_row = tid >> 3;          // + it*32
    int a_kq  = (tid & 7) * 4;     // k within chunk (elems)

    // ldmatrix source addresses (byte, shared space)
    int l15 = lane & 15;
    int khalf = (lane >> 4) * 8;   // A: k offset 8 for matrices 2,3
    uint32_t aH_base = (uint32_t)__cvta_generic_to_shared(sAh)
                     + (uint32_t)(((wm * 32 + l15) * A_PH + khalf) * 2);
    uint32_t aL_base = aH_base + (uint32_t)(M_TILE * A_PH * 2);
    int b_krow = (lane & 7) + ((lane & 8) ? 8 : 0);
    int b_noff = (lane & 16) ? 8 : 0;
    uint32_t b_base = (uint32_t)__cvta_generic_to_shared(sB)
                    + (uint32_t)((b_krow * B_PH + wn * 64 + b_noff) * 2);

    float acc[2][8][4];
    #pragma unroll
    for (int mi = 0; mi < 2; mi++)
        #pragma unroll
        for (int ni = 0; ni < 8; ni++)
            #pragma unroll
            for (int t = 0; t < 4; t++) acc[mi][ni][t] = 0.f;

    const uint4* wh4 = (const uint4*)Wh;      // [128][16] uint4 rows

    float4 rA[4]; uint4 rB[2];
    // prologue: load chunk 0
    #pragma unroll
    for (int it = 0; it < 4; it++) {
        int gr = m0 + it * 32 + a_row;
        rA[it] = make_float4(0.f, 0.f, 0.f, 0.f);
        if (gr < N_NODES) rA[it] = *(const float4*)(in + (size_t)gr * HID + a_kq);
    }
    {
        int t0 = tid, t1 = tid + 256;         // 512 uint4 per B chunk
        rB[0] = wh4[t0];
        rB[1] = wh4[t1];
    }

    #pragma unroll
    for (int c = 0; c < 4; c++) {
        // commit chunk c to smem
        #pragma unroll
        for (int it = 0; it < 4; it++) {
            float4 v = rA[it];
            __half2 h01 = __floats2half2_rn(v.x, v.y);
            __half2 h23 = __floats2half2_rn(v.z, v.w);
            float2 f01 = __half22float2(h01);
            float2 f23 = __half22float2(h23);
            __half2 l01 = __floats2half2_rn(v.x - f01.x, v.y - f01.y);
            __half2 l23 = __floats2half2_rn(v.z - f23.x, v.w - f23.y);
            int row = it * 32 + a_row;
            uint32_t* ph = (uint32_t*)&sAh[row * A_PH + a_kq];
            uint32_t* pl = (uint32_t*)&sAl[row * A_PH + a_kq];
            ph[0] = *(uint32_t*)&h01; ph[1] = *(uint32_t*)&h23;
            pl[0] = *(uint32_t*)&l01; pl[1] = *(uint32_t*)&l23;
        }
        {
            int t0 = tid, t1 = tid + 256;
            int r0 = t0 >> 4, c0 = (t0 & 15) * 8;
            int r1 = t1 >> 4, c1 = (t1 & 15) * 8;
            *(uint4*)&sB[r0 * B_PH + c0] = rB[0];
            *(uint4*)&sB[r1 * B_PH + c1] = rB[1];
        }
        __syncthreads();

        // prefetch chunk c+1
        if (c < 3) {
            #pragma unroll
            for (int it = 0; it < 4; it++) {
                int gr = m0 + it * 32 + a_row;
                rA[it] = make_float4(0.f, 0.f, 0.f, 0.f);
                if (gr < N_NODES)
                    rA[it] = *(const float4*)(in + (size_t)gr * HID + (c + 1) * BK + a_kq);
            }
            rB[0] = wh4[(c + 1) * 512 + tid];
            rB[1] = wh4[(c + 1) * 512 + tid + 256];
        }

        // MMA chain: ldmatrix fragment loads
        #pragma unroll
        for (int ks = 0; ks < 2; ks++) {
            uint32_t ah[2][4], al[2][4], b[8][2];
            #pragma unroll
            for (int mi = 0; mi < 2; mi++) {
                uint32_t off = (uint32_t)((mi * 16 * A_PH + ks * 16) * 2);
                LDSM_X4(ah[mi][0], ah[mi][1], ah[mi][2], ah[mi][3], aH_base + off);
                LDSM_X4(al[mi][0], al[mi][1], al[mi][2], al[mi][3], aL_base + off);
            }
            #pragma unroll
            for (int n2 = 0; n2 < 4; n2++) {
                uint32_t off = (uint32_t)((ks * 16 * B_PH + n2 * 16) * 2);
                LDSM_X4T(b[2 * n2][0], b[2 * n2][1], b[2 * n2 + 1][0], b[2 * n2 + 1][1],
                         b_base + off);
            }
            #pragma unroll
            for (int ni = 0; ni < 8; ni++)
                #pragma unroll
                for (int mi = 0; mi < 2; mi++) {
                    mma_f16(acc[mi][ni], ah[mi], b[ni]);
                    mma_f16(acc[mi][ni], al[mi], b[ni]);
                }
        }
        __syncthreads();
    }

    // epilogue: store g_xh (fp16) + fused alpha partial dots (fp32, exact)
    #pragma unroll
    for (int mi = 0; mi < 2; mi++) {
        int rA_ = wm * 32 + g + mi * 16;
        int rB_ = rA_ + 8;
        int gA = m0 + rA_, gB = m0 + rB_;
        float sA_ = 0.f, dA_ = 0.f, sB_ = 0.f, dB_ = 0.f;
        #pragma unroll
        for (int ni = 0; ni < 8; ni++) {
            int cc = wn * 64 + ni * 8 + q * 2;
            float v0 = acc[mi][ni][0], v1 = acc[mi][ni][1];
            float v2 = acc[mi][ni][2], v3 = acc[mi][ni][3];
            sA_ += v0 * s_as[cc] + v1 * s_as[cc + 1];
            dA_ += v0 * s_ad[cc] + v1 * s_ad[cc + 1];
            sB_ += v2 * s_as[cc] + v3 * s_as[cc + 1];
            dB_ += v2 * s_ad[cc] + v3 * s_ad[cc + 1];
            if (gA < N_NODES)
                *(__half2*)(g_xh + (size_t)gA * HID + cc) = __floats2half2_rn(v0, v1);
            if (gB < N_NODES)
                *(__half2*)(g_xh + (size_t)gB * HID + cc) = __floats2half2_rn(v2, v3);
        }
        sA_ += __shfl_xor_sync(0xffffffffu, sA_, 1); sA_ += __shfl_xor_sync(0xffffffffu, sA_, 2);
        dA_ += __shfl_xor_sync(0xffffffffu, dA_, 1); dA_ += __shfl_xor_sync(0xffffffffu, dA_, 2);
        sB_ += __shfl_xor_sync(0xffffffffu, sB_, 1); sB_ += __shfl_xor_sync(0xffffffffu, sB_, 2);
        dB_ += __shfl_xor_sync(0xffffffffu, dB_, 1); dB_ += __shfl_xor_sync(0xffffffffu, dB_, 2);
        if (q == 0) {
            s_ps[wn][rA_] = sA_; s_pd[wn][rA_] = dA_;
            s_ps[wn][rB_] = sB_; s_pd[wn][rB_] = dB_;
        }
    }
    __syncthreads();
    if (tid < M_TILE) {
        int gm = m0 + tid;
        if (gm < N_NODES) {
            g_as[gm] = s_ps[0][tid] + s_ps[1][tid];
            g_ad[gm] = s_pd[0][tid] + s_pd[1][tid];
        }
    }
}

// ---------------- aggregation: warp/node, online softmax, smem pair bcast ----
// R11 version (measured best).
__device__ __forceinline__ float leaky(float t) {
    return t > 0.f ? t : NEG_SLOPE * t;
}

__global__ __launch_bounds__(256) void agg_kernel(
    const float* __restrict__ bias, float* __restrict__ dout, int last)
{
    __shared__ uint2 s_ew[8][32];    // per-warp (w, src) pair table
    int node = (blockIdx.x * blockDim.x + threadIdx.x) >> 5;
    int lane = threadIdx.x & 31;
    int wid  = (threadIdx.x >> 5) & 7;
    if (node >= N_NODES) return;
    int start = g_off[node];
    int end   = g_off[node + 1];
    float adv = g_ad[node];

    float m = -INFINITY;
    float den = 0.f;
    float4 acc = make_float4(0.f, 0.f, 0.f, 0.f);

    for (int i0 = start; i0 < end; i0 += 32) {
        int n = end - i0; if (n > 32) n = 32;
        int   s_l = 0; float e_l = -INFINITY;
        if (lane < n) {
            s_l = g_csrc[i0 + lane];
            e_l = leaky(g_as[s_l] + adv);
        }
        float bm = e_l;
        #pragma unroll
        for (int o = 16; o; o >>= 1) bm = fmaxf(bm, __shfl_xor_sync(0xffffffffu, bm, o));
        if (bm > m) {
            float f = __expf(m - bm);
            acc.x *= f; acc.y *= f; acc.z *= f; acc.w *= f;
            den *= f;
            m = bm;
        }
        float w_l = (lane < n) ? __expf(e_l - m) : 0.f;
        den += w_l;
        s_ew[wid][lane] = make_uint2(__float_as_uint(w_l), (uint32_t)s_l);
        __syncwarp();
        for (int j = 0; j < n; j++) {
            uint2 ew = s_ew[wid][j];               // LDS.64 broadcast
            float w = __uint_as_float(ew.x);
            int   s = (int)ew.y;
            uint2 raw = *((const uint2*)(g_xh + (size_t)s * HID) + lane);
            float2 f0 = __half22float2(*(const __half2*)&raw.x);
            float2 f1 = __half22float2(*(const __half2*)&raw.y);
            acc.x += w * f0.x; acc.y += w * f0.y;
            acc.z += w * f1.x; acc.w += w * f1.y;
        }
        __syncwarp();
    }
    #pragma unroll
    for (int o = 16; o; o >>= 1) den += __shfl_xor_sync(0xffffffffu, den, o);
    float inv = 1.0f / (den + EPS);

    float4 b4 = *(const float4*)(bias + lane * 4);
    acc.x = acc.x * inv + b4.x; acc.y = acc.y * inv + b4.y;
    acc.z = acc.z * inv + b4.z; acc.w = acc.w * inv + b4.w;

    if (last) {
        *(float4*)(dout + (size_t)node * HID + lane * 4) = acc;
    } else {
        acc.x = fmaxf(acc.x, 0.f); acc.y = fmaxf(acc.y, 0.f);
        acc.z = fmaxf(acc.z, 0.f); acc.w = fmaxf(acc.w, 0.f);
        *(float4*)(g_h + (size_t)node * HID + lane * 4) = acc;
    }
}

// ---------------- launch -----------------------------------------------------
extern "C" void kernel_launch(void* const* d_in, const int* in_sizes, int n_in,
                              void* d_out, int out_size)
{
    const float* z     = (const float*)d_in[0];
    const int*   ei    = (const int*)  d_in[1];
    const float* Ws    = (const float*)d_in[2];
    const float* a_src = (const float*)d_in[3];
    const float* a_dst = (const float*)d_in[4];
    const float* bias  = (const float*)d_in[5];
    float* out = (float*)d_out;

    float*  d_gh;  cudaGetSymbolAddress((void**)&d_gh, g_h);
    __half* d_wh;  cudaGetSymbolAddress((void**)&d_wh, g_wh);
    int*    d_deg; cudaGetSymbolAddress((void**)&d_deg, g_deg);

    int warp_blocks = (N_NODES * 32 + 255) / 256;

    cudaMemsetAsync(d_deg, 0, N_PAD * sizeof(int));
    prep_w_kernel<<<(3 * HID * HID / 2 + 255) / 256, 256>>>(Ws);     // launch 1
    count_kernel<<<(N_EDGES / 4 + 255) / 256, 256>>>(ei);            // launch 2
    scan_kernel<<<1, 1024>>>();                                      // launch 3
    // launch 4 = gemm0 (ncu capture slot)
    gemm_mma_kernel<<<M_BLOCKS, 256, GEMM_DYN_SMEM>>>(z, d_wh, a_src, a_dst);
    fill_kernel<<<(N_EDGES / 4 + N_NODES + 255) / 256, 256>>>(ei);   // launch 5
    agg_kernel<<<warp_blocks, 256>>>(bias, out, 0);

    for (int l = 1; l < 3; l++) {
        gemm_mma_kernel<<<M_BLOCKS, 256, GEMM_DYN_SMEM>>>(
            d_gh, d_wh + (size_t)l * HID * HID, a_src + l * HID, a_dst + l * HID);
        agg_kernel<<<warp_blocks, 256>>>(bias + l * HID, out, l == 2);
    }
}

// round 14
// speedup vs baseline: 1.1340x; 1.0825x over previous
#include <cuda_runtime.h>
#include <cuda_fp16.h>
#include <math.h>
#include <stdint.h>

#define N_NODES 50000
#define N_PAD   53248            // padded for int4 scan reads
#define N_EDGES 800000
#define E_TOT   (N_EDGES + N_NODES)   // with self loops
#define HID     128
#define NEG_SLOPE 0.2f
#define EPS 1e-16f

#define M_TILE   128
#define M_BLOCKS ((N_NODES + M_TILE - 1) / M_TILE)   // 391
#define BK 32                 // k (fp16 elems) per chunk
#define A_PH 40               // half pitch for A tiles (32 + 8 pad) -> 80B rows
#define B_PH 136              // half pitch for B chunk (128 + 8)    -> 272B rows
#define GEMM_DYN_SMEM ((2 * M_TILE * A_PH + BK * B_PH) * 2)   // 29184 B

// ---------------- scratch (device globals; no allocation allowed) -----------
__device__ __half  g_xh[(size_t)N_NODES * HID];  // x = h @ W, fp16 (gather source)
__device__ float   g_h [(size_t)N_NODES * HID];  // layer activations (fp32)
__device__ float   g_as[N_NODES];
__device__ float   g_ad[N_NODES];
__device__ __half  g_wh[3 * HID * HID];          // W fp16 image: [l][k][n]
__device__ int     g_deg[N_PAD];
__device__ int     g_off[N_NODES + 1];
__device__ int     g_cur[N_NODES];
__device__ int     g_csrc[E_TOT];

// ---------------- helpers -----------------------------------------------------
__device__ __forceinline__ void mma_f16(float* d, const uint32_t* a, const uint32_t* b) {
    asm volatile(
        "mma.sync.aligned.m16n8k16.row.col.f32.f16.f16.f32 "
        "{%0,%1,%2,%3}, {%4,%5,%6,%7}, {%8,%9}, {%0,%1,%2,%3};"
        : "+f"(d[0]), "+f"(d[1]), "+f"(d[2]), "+f"(d[3])
        : "r"(a[0]), "r"(a[1]), "r"(a[2]), "r"(a[3]), "r"(b[0]), "r"(b[1]));
}
#define LDSM_X4(R0, R1, R2, R3, ADDR) \
    asm volatile("ldmatrix.sync.aligned.m8n8.x4.shared.b16 {%0,%1,%2,%3}, [%4];" \
        : "=r"(R0), "=r"(R1), "=r"(R2), "=r"(R3) : "r"(ADDR))
#define LDSM_X4T(R0, R1, R2, R3, ADDR) \
    asm volatile("ldmatrix.sync.aligned.m8n8.x4.trans.shared.b16 {%0,%1,%2,%3}, [%4];" \
        : "=r"(R0), "=r"(R1), "=r"(R2), "=r"(R3) : "r"(ADDR))

// ---------------- prep: W -> plain fp16 image [l][k][n] ----------------------
__global__ void prep_w_kernel(const float* __restrict__ Ws) {
    int i = blockIdx.x * blockDim.x + threadIdx.x;   // over 3*128*128/2 half2
    if (i >= 3 * HID * HID / 2) return;
    float2 v = ((const float2*)Ws)[i];
    ((__half2*)g_wh)[i] = __floats2half2_rn(v.x, v.y);
}

// ---------------- CSR build (4 edges/thread) ----------------------------------
__global__ void count_kernel(const int* __restrict__ ei) {
    int t = blockIdx.x * blockDim.x + threadIdx.x;     // over N_EDGES/4
    if (t >= N_EDGES / 4) return;
    int4 d4 = ((const int4*)(ei + N_EDGES))[t];
    atomicAdd(&g_deg[d4.x], 1);
    atomicAdd(&g_deg[d4.y], 1);
    atomicAdd(&g_deg[d4.z], 1);
    atomicAdd(&g_deg[d4.w], 1);
}
// single-block exclusive scan, 4 elements/thread; +1/node folds in self-loops
__global__ void scan_kernel() {
    __shared__ int warp_sums[32];
    __shared__ int s_carry;
    int tid = threadIdx.x, lane = tid & 31, wid = tid >> 5;
    if (tid == 0) { g_off[0] = 0; s_carry = 0; }
    __syncthreads();
    for (int base = 0; base < N_NODES; base += 4096) {
        int i = base + tid * 4;
        int4 v = *(const int4*)(g_deg + i);            // padded zeros beyond N_NODES
        int sl = (i < N_NODES) ? 1 : 0;                // self-loop (N_NODES % 4 == 0)
        int t0 = v.x + sl, t1 = t0 + v.y + sl, t2 = t1 + v.z + sl, t3 = t2 + v.w + sl;
        int x = t3;
        #pragma unroll
        for (int d = 1; d < 32; d <<= 1) {
            int t = __shfl_up_sync(0xffffffffu, x, d);
            if (lane >= d) x += t;
        }
        if (lane == 31) warp_sums[wid] = x;
        __syncthreads();
        if (wid == 0) {
            int w = warp_sums[lane];
            #pragma unroll
            for (int d = 1; d < 32; d <<= 1) {
                int t = __shfl_up_sync(0xffffffffu, w, d);
                if (lane >= d) w += t;
            }
            warp_sums[lane] = w;
        }
        __syncthreads();
        int excl = x - t3 + ((wid > 0) ? warp_sums[wid - 1] : 0) + s_carry;
        if (i < N_NODES) {
            g_off[i + 1] = excl + t0; g_cur[i + 0] = excl;
            g_off[i + 2] = excl + t1; g_cur[i + 1] = excl + t0;
            g_off[i + 3] = excl + t2; g_cur[i + 2] = excl + t1;
            g_off[i + 4] = excl + t3; g_cur[i + 3] = excl + t2;
        }
        __syncthreads();
        if (tid == 1023) s_carry = excl + t3;
        __syncthreads();
    }
}
__global__ void fill_kernel(const int* __restrict__ ei) {
    int t = blockIdx.x * blockDim.x + threadIdx.x;
    if (t < N_EDGES / 4) {
        int4 s4 = ((const int4*)ei)[t];
        int4 d4 = ((const int4*)(ei + N_EDGES))[t];
        g_csrc[atomicAdd(&g_cur[d4.x], 1)] = s4.x;
        g_csrc[atomicAdd(&g_cur[d4.y], 1)] = s4.y;
        g_csrc[atomicAdd(&g_cur[d4.z], 1)] = s4.z;
        g_csrc[atomicAdd(&g_cur[d4.w], 1)] = s4.w;
    } else {
        int node = t - N_EDGES / 4;
        if (node < N_NODES)
            g_csrc[atomicAdd(&g_cur[node], 1)] = node;   // self loop
    }
}

// ---------------- GEMM: fp16 m16n8k16 2-term, ldmatrix fragment loads --------
__global__ void __launch_bounds__(256, 2)
gemm_mma_kernel(const float* __restrict__ in, const __half* __restrict__ Wh,
                const float* __restrict__ a_s, const float* __restrict__ a_d)
{
    extern __shared__ __half dsm[];
    __half* sAh = dsm;                        // [M_TILE][A_PH]
    __half* sAl = sAh + M_TILE * A_PH;        // [M_TILE][A_PH]
    __half* sB  = sAl + M_TILE * A_PH;        // [BK][B_PH]  (k rows, n cols)

    __shared__ float s_as[HID], s_ad[HID];
    __shared__ float s_ps[2][M_TILE], s_pd[2][M_TILE];

    int tid = threadIdx.x, lane = tid & 31, wid = tid >> 5;
    int wm = wid & 3;        // warp M tile: 32 rows
    int wn = wid >> 2;       // warp N tile: 64 cols
    int m0 = blockIdx.x * M_TILE;
    int q = lane & 3, g = lane >> 2;

    for (int i = tid; i < HID; i += 256) { s_as[i] = a_s[i]; s_ad[i] = a_d[i]; }

    int a_row = tid >> 3;          // + it*32
    int a_kq  = (tid & 7) * 4;     // k within chunk (elems)

    int l15 = lane & 15;
    int khalf = (lane >> 4) * 8;
    uint32_t aH_base = (uint32_t)__cvta_generic_to_shared(sAh)
                     + (uint32_t)(((wm * 32 + l15) * A_PH + khalf) * 2);
    uint32_t aL_base = aH_base + (uint32_t)(M_TILE * A_PH * 2);
    int b_krow = (lane & 7) + ((lane & 8) ? 8 : 0);
    int b_noff = (lane & 16) ? 8 : 0;
    uint32_t b_base = (uint32_t)__cvta_generic_to_shared(sB)
                    + (uint32_t)((b_krow * B_PH + wn * 64 + b_noff) * 2);

    float acc[2][8][4];
    #pragma unroll
    for (int mi = 0; mi < 2; mi++)
        #pragma unroll
        for (int ni = 0; ni < 8; ni++)
            #pragma unroll
            for (int t = 0; t < 4; t++) acc[mi][ni][t] = 0.f;

    const uint4* wh4 = (const uint4*)Wh;      // [128][16] uint4 rows

    float4 rA[4]; uint4 rB[2];
    #pragma unroll
    for (int it = 0; it < 4; it++) {
        int gr = m0 + it * 32 + a_row;
        rA[it] = make_float4(0.f, 0.f, 0.f, 0.f);
        if (gr < N_NODES) rA[it] = *(const float4*)(in + (size_t)gr * HID + a_kq);
    }
    rB[0] = wh4[tid];
    rB[1] = wh4[tid + 256];

    #pragma unroll
    for (int c = 0; c < 4; c++) {
        #pragma unroll
        for (int it = 0; it < 4; it++) {
            float4 v = rA[it];
            __half2 h01 = __floats2half2_rn(v.x, v.y);
            __half2 h23 = __floats2half2_rn(v.z, v.w);
            float2 f01 = __half22float2(h01);
            float2 f23 = __half22float2(h23);
            __half2 l01 = __floats2half2_rn(v.x - f01.x, v.y - f01.y);
            __half2 l23 = __floats2half2_rn(v.z - f23.x, v.w - f23.y);
            int row = it * 32 + a_row;
            uint32_t* ph = (uint32_t*)&sAh[row * A_PH + a_kq];
            uint32_t* pl = (uint32_t*)&sAl[row * A_PH + a_kq];
            ph[0] = *(uint32_t*)&h01; ph[1] = *(uint32_t*)&h23;
            pl[0] = *(uint32_t*)&l01; pl[1] = *(uint32_t*)&l23;
        }
        {
            int t0 = tid, t1 = tid + 256;
            int r0 = t0 >> 4, c0 = (t0 & 15) * 8;
            int r1 = t1 >> 4, c1 = (t1 & 15) * 8;
            *(uint4*)&sB[r0 * B_PH + c0] = rB[0];
            *(uint4*)&sB[r1 * B_PH + c1] = rB[1];
        }
        __syncthreads();

        if (c < 3) {
            #pragma unroll
            for (int it = 0; it < 4; it++) {
                int gr = m0 + it * 32 + a_row;
                rA[it] = make_float4(0.f, 0.f, 0.f, 0.f);
                if (gr < N_NODES)
                    rA[it] = *(const float4*)(in + (size_t)gr * HID + (c + 1) * BK + a_kq);
            }
            rB[0] = wh4[(c + 1) * 512 + tid];
            rB[1] = wh4[(c + 1) * 512 + tid + 256];
        }

        #pragma unroll
        for (int ks = 0; ks < 2; ks++) {
            uint32_t ah[2][4], al[2][4], b[8][2];
            #pragma unroll
            for (int mi = 0; mi < 2; mi++) {
                uint32_t off = (uint32_t)((mi * 16 * A_PH + ks * 16) * 2);
                LDSM_X4(ah[mi][0], ah[mi][1], ah[mi][2], ah[mi][3], aH_base + off);
                LDSM_X4(al[mi][0], al[mi][1], al[mi][2], al[mi][3], aL_base + off);
            }
            #pragma unroll
            for (int n2 = 0; n2 < 4; n2++) {
                uint32_t off = (uint32_t)((ks * 16 * B_PH + n2 * 16) * 2);
                LDSM_X4T(b[2 * n2][0], b[2 * n2][1], b[2 * n2 + 1][0], b[2 * n2 + 1][1],
                         b_base + off);
            }
            #pragma unroll
            for (int ni = 0; ni < 8; ni++)
                #pragma unroll
                for (int mi = 0; mi < 2; mi++) {
                    mma_f16(acc[mi][ni], ah[mi], b[ni]);
                    mma_f16(acc[mi][ni], al[mi], b[ni]);
                }
        }
        __syncthreads();
    }

    // epilogue: store g_xh (fp16) + fused alpha partial dots (fp32, exact)
    #pragma unroll
    for (int mi = 0; mi < 2; mi++) {
        int rA_ = wm * 32 + g + mi * 16;
        int rB_ = rA_ + 8;
        int gA = m0 + rA_, gB = m0 + rB_;
        float sA_ = 0.f, dA_ = 0.f, sB_ = 0.f, dB_ = 0.f;
        #pragma unroll
        for (int ni = 0; ni < 8; ni++) {
            int cc = wn * 64 + ni * 8 + q * 2;
            float v0 = acc[mi][ni][0], v1 = acc[mi][ni][1];
            float v2 = acc[mi][ni][2], v3 = acc[mi][ni][3];
            sA_ += v0 * s_as[cc] + v1 * s_as[cc + 1];
            dA_ += v0 * s_ad[cc] + v1 * s_ad[cc + 1];
            sB_ += v2 * s_as[cc] + v3 * s_as[cc + 1];
            dB_ += v2 * s_ad[cc] + v3 * s_ad[cc + 1];
            if (gA < N_NODES)
                *(__half2*)(g_xh + (size_t)gA * HID + cc) = __floats2half2_rn(v0, v1);
            if (gB < N_NODES)
                *(__half2*)(g_xh + (size_t)gB * HID + cc) = __floats2half2_rn(v2, v3);
        }
        sA_ += __shfl_xor_sync(0xffffffffu, sA_, 1); sA_ += __shfl_xor_sync(0xffffffffu, sA_, 2);
        dA_ += __shfl_xor_sync(0xffffffffu, dA_, 1); dA_ += __shfl_xor_sync(0xffffffffu, dA_, 2);
        sB_ += __shfl_xor_sync(0xffffffffu, sB_, 1); sB_ += __shfl_xor_sync(0xffffffffu, sB_, 2);
        dB_ += __shfl_xor_sync(0xffffffffu, dB_, 1); dB_ += __shfl_xor_sync(0xffffffffu, dB_, 2);
        if (q == 0) {
            s_ps[wn][rA_] = sA_; s_pd[wn][rA_] = dA_;
            s_ps[wn][rB_] = sB_; s_pd[wn][rB_] = dB_;
        }
    }
    __syncthreads();
    if (tid < M_TILE) {
        int gm = m0 + tid;
        if (gm < N_NODES) {
            g_as[gm] = s_ps[0][tid] + s_ps[1][tid];
            g_ad[gm] = s_pd[0][tid] + s_pd[1][tid];
        }
    }
}

// ---------------- aggregation: warp/node, online softmax, smem pair bcast ----
__device__ __forceinline__ float leaky(float t) {
    return t > 0.f ? t : NEG_SLOPE * t;
}

__global__ __launch_bounds__(256) void agg_kernel(
    const float* __restrict__ bias, float* __restrict__ dout, int last)
{
    __shared__ uint2 s_ew[8][32];    // per-warp (w, src) pair table
    int node = (blockIdx.x * blockDim.x + threadIdx.x) >> 5;
    int lane = threadIdx.x & 31;
    int wid  = (threadIdx.x >> 5) & 7;
    if (node >= N_NODES) return;
    int start = g_off[node];
    int end   = g_off[node + 1];
    float adv = g_ad[node];

    float m = -INFINITY;
    float den = 0.f;
    float4 acc = make_float4(0.f, 0.f, 0.f, 0.f);

    for (int i0 = start; i0 < end; i0 += 32) {
        int n = end - i0; if (n > 32) n = 32;
        int   s_l = 0; float e_l = -INFINITY;
        if (lane < n) {
            s_l = g_csrc[i0 + lane];
            e_l = leaky(g_as[s_l] + adv);
        }
        float bm = e_l;
        #pragma unroll
        for (int o = 16; o; o >>= 1) bm = fmaxf(bm, __shfl_xor_sync(0xffffffffu, bm, o));
        if (bm > m) {
            float f = __expf(m - bm);
            acc.x *= f; acc.y *= f; acc.z *= f; acc.w *= f;
            den *= f;
            m = bm;
        }
        float w_l = (lane < n) ? __expf(e_l - m) : 0.f;
        den += w_l;
        s_ew[wid][lane] = make_uint2(__float_as_uint(w_l), (uint32_t)s_l);
        __syncwarp();
        for (int j = 0; j < n; j++) {
            uint2 ew = s_ew[wid][j];               // LDS.64 broadcast
            float w = __uint_as_float(ew.x);
            int   s = (int)ew.y;
            uint2 raw = *((const uint2*)(g_xh + (size_t)s * HID) + lane);
            float2 f0 = __half22float2(*(const __half2*)&raw.x);
            float2 f1 = __half22float2(*(const __half2*)&raw.y);
            acc.x += w * f0.x; acc.y += w * f0.y;
            acc.z += w * f1.x; acc.w += w * f1.y;
        }
        __syncwarp();
    }
    #pragma unroll
    for (int o = 16; o; o >>= 1) den += __shfl_xor_sync(0xffffffffu, den, o);
    float inv = 1.0f / (den + EPS);

    float4 b4 = *(const float4*)(bias + lane * 4);
    acc.x = acc.x * inv + b4.x; acc.y = acc.y * inv + b4.y;
    acc.z = acc.z * inv + b4.z; acc.w = acc.w * inv + b4.w;

    if (last) {
        *(float4*)(dout + (size_t)node * HID + lane * 4) = acc;
    } else {
        acc.x = fmaxf(acc.x, 0.f); acc.y = fmaxf(acc.y, 0.f);
        acc.z = fmaxf(acc.z, 0.f); acc.w = fmaxf(acc.w, 0.f);
        *(float4*)(g_h + (size_t)node * HID + lane * 4) = acc;
    }
}

// ---------------- launch -----------------------------------------------------
extern "C" void kernel_launch(void* const* d_in, const int* in_sizes, int n_in,
                              void* d_out, int out_size)
{
    const float* z     = (const float*)d_in[0];
    const int*   ei    = (const int*)  d_in[1];
    const float* Ws    = (const float*)d_in[2];
    const float* a_src = (const float*)d_in[3];
    const float* a_dst = (const float*)d_in[4];
    const float* bias  = (const float*)d_in[5];
    float* out = (float*)d_out;

    float*  d_gh;  cudaGetSymbolAddress((void**)&d_gh, g_h);
    __half* d_wh;  cudaGetSymbolAddress((void**)&d_wh, g_wh);
    int*    d_deg; cudaGetSymbolAddress((void**)&d_deg, g_deg);

    // one-time host-side resources (no device allocation)
    static cudaStream_t s2 = nullptr;
    static cudaEvent_t evFork = nullptr, evJoin = nullptr;
    if (s2 == nullptr) {
        cudaStreamCreateWithFlags(&s2, cudaStreamNonBlocking);
        cudaEventCreateWithFlags(&evFork, cudaEventDisableTiming);
        cudaEventCreateWithFlags(&evJoin, cudaEventDisableTiming);
    }

    int warp_blocks = (N_NODES * 32 + 255) / 256;

    // fork: CSR chain on s2, concurrent with prep_w + gemm0 on the main stream
    cudaEventRecord(evFork, 0);
    cudaStreamWaitEvent(s2, evFork, 0);
    cudaMemsetAsync(d_deg, 0, N_PAD * sizeof(int), s2);
    count_kernel<<<(N_EDGES / 4 + 255) / 256, 256, 0, s2>>>(ei);
    scan_kernel<<<1, 1024, 0, s2>>>();
    fill_kernel<<<(N_EDGES / 4 + N_NODES + 255) / 256, 256, 0, s2>>>(ei);
    cudaEventRecord(evJoin, s2);

    // main stream: layer-0 linear transform (independent of CSR)
    prep_w_kernel<<<(3 * HID * HID / 2 + 255) / 256, 256>>>(Ws);
    gemm_mma_kernel<<<M_BLOCKS, 256, GEMM_DYN_SMEM>>>(z, d_wh, a_src, a_dst);

    // join: agg0 needs the CSR
    cudaStreamWaitEvent(0, evJoin, 0);
    agg_kernel<<<warp_blocks, 256>>>(bias, out, 0);

    for (int l = 1; l < 3; l++) {
        gemm_mma_kernel<<<M_BLOCKS, 256, GEMM_DYN_SMEM>>>(
            d_gh, d_wh + (size_t)l * HID * HID, a_src + l * HID, a_dst + l * HID);
        agg_kernel<<<warp_blocks, 256>>>(bias + l * HID, out, l == 2);
    }
}